// round 10
// baseline (speedup 1.0000x reference)
#include <cuda_runtime.h>
#include <cuda_bf16.h>
#include <math.h>

#define IH 1024
#define IW 1024
#define NB 8
#define CH (IH * IW)
#define TS 64     // tile size (both dims)
#define SI 72     // s_img stride; col c <-> gx = x0-4+c (0..71), row r <-> gy = y0-3+r (0..69)
#define SG 72     // s_gm stride; col c <-> gx = x0-2+c (0..67), row r <-> gy = y0-2+r (0..67)
#define ST 72     // s_t stride (bytes); col c <-> gx = x0-1+c (0..65), row r <-> gy = y0-1+r (0..65)

#define T0 0.1989123673796580f
#define T1 0.6681786379192989f
#define T2 1.4966057626654890f
#define T3 5.0273394921258481f
#define INV3 0.3333333333333333f

__device__ __forceinline__ int quant_q(float sx, float sy) {
    float ax = fabsf(sx), ay = fabsf(sy);
    int mm = (int)(ay > T0 * ax) + (int)(ay > T1 * ax)
           + (int)(ay > T2 * ax) + (int)(ay > T3 * ax);
    int neg = (__float_as_int(sx) ^ __float_as_int(sy)) < 0;
    return neg ? 4 - mm : 4 + mm;
}

// thin-edge code {0,1,2} (t = code * 0.5)
__device__ __forceinline__ int nms_code(int k, float gmc,
                                        float g00, float g01, float g02,
                                        float g10,            float g12,
                                        float g20, float g21, float g22) {
    float mx0 = fmaxf(g10, g12);   // k=0: (0,±1)
    float mx1 = fmaxf(g02, g20);   // k=1: (-1,1)/(1,-1)
    float mx2 = fmaxf(g01, g21);   // k=2: (±1,0)
    float mx3 = fmaxf(g00, g22);   // k=3: (-1,-1)/(1,1)
    float mxa = (k & 1) ? mx1 : mx0;
    float mxb = (k & 1) ? mx3 : mx2;
    float mx  = (k & 2) ? mxb : mxa;
    float thin = (gmc > mx) ? gmc : 0.0f;
    return (int)(thin > 0.5f) + (int)(thin > 1.0f);
}

// sobel at gm-coord (R,C): taps s_img rows R..R+2, cols C+1..C+3 (canonical u/v form)
__device__ __forceinline__ void sobel_at(const float* __restrict__ s_img, int R, int C,
                                         float& sx, float& sy) {
    const float* ip = s_img + R * SI + (C + 1);
    float a0 = ip[0],      a1 = ip[1],          a2 = ip[2];
    float b0 = ip[SI],                          b2 = ip[SI + 2];
    float c0 = ip[2 * SI], c1 = ip[2 * SI + 1], c2 = ip[2 * SI + 2];
    float u0 = a2 - a0, v0 = 0.5f * (a0 + a2) + a1;
    float u1 = b2 - b0;
    float u2 = c2 - c0, v2 = 0.5f * (c0 + c2) + c1;
    sx = (0.5f * (u0 + u2) + u1) * INV3;
    sy = (v2 - v0) * INV3;
}

// ======================= interior (pair-vectorized) =======================
__device__ __forceinline__ void body_int(
    const float* __restrict__ imgb, float* __restrict__ out,
    int b, int x0, int y0, int tx, int ty, int tid,
    float* __restrict__ s_img, float* __restrict__ s_gm, unsigned char* __restrict__ s_t)
{
    const size_t plane = (size_t)NB * CH;
    float* o_gx = out;
    float* o_gy = out + plane;
    float* o_gm = out + 2 * plane;
    float* o_or = out + 3 * plane;
    float* o_te = out + 4 * plane;

    // ---- P1: channel-summed image, 70 rows x 18 float4 groups = 1260 tasks ----
    {
        const float4* base = (const float4*)(imgb + (size_t)(y0 - 3) * IW + (x0 - 4));
        #pragma unroll
        for (int p = 0; p < 5; p++) {
            int idx = tid + 256 * p;
            if (idx < 1260) {
                int r = idx / 18, g = idx % 18;
                const float4* ptr = base + r * (IW / 4) + g;
                float4 v0 = ptr[0], v1 = ptr[CH / 4], v2 = ptr[2 * (CH / 4)];
                float4 s;
                s.x = v0.x + v1.x + v2.x; s.y = v0.y + v1.y + v2.y;
                s.z = v0.z + v1.z + v2.z; s.w = v0.w + v1.w + v2.w;
                *(float4*)&s_img[r * SI + 4 * g] = s;
            }
        }
    }
    __syncthreads();

    // ---- P2: gm. main: rows 2..65, col pair c=2tx (cols 0..63) ----
    {
        int r0 = 2 + 8 * ty, c = 2 * tx;
        const float* ip = s_img + r0 * SI + (c + 1);   // 4 taps cover px c and c+1
        float f0 = ip[0], f1 = ip[1], f2 = ip[2], f3 = ip[3];
        float ua0 = f2 - f0, va0 = 0.5f * (f0 + f2) + f1;
        float ub0 = f3 - f1, vb0 = 0.5f * (f1 + f3) + f2;
        f0 = ip[SI]; f1 = ip[SI + 1]; f2 = ip[SI + 2]; f3 = ip[SI + 3];
        float ua1 = f2 - f0, va1 = 0.5f * (f0 + f2) + f1;
        float ub1 = f3 - f1, vb1 = 0.5f * (f1 + f3) + f2;
        #pragma unroll
        for (int j = 0; j < 8; j++) {
            const float* rp = ip + (j + 2) * SI;
            f0 = rp[0]; f1 = rp[1]; f2 = rp[2]; f3 = rp[3];
            float ua2 = f2 - f0, va2 = 0.5f * (f0 + f2) + f1;
            float ub2 = f3 - f1, vb2 = 0.5f * (f1 + f3) + f2;
            float sxa = (0.5f * (ua0 + ua2) + ua1) * INV3;
            float sya = (va2 - va0) * INV3;
            float sxb = (0.5f * (ub0 + ub2) + ub1) * INV3;
            float syb = (vb2 - vb0) * INV3;
            float2 g = make_float2(sqrtf(sxa * sxa + sya * sya),
                                   sqrtf(sxb * sxb + syb * syb));
            *(float2*)&s_gm[(r0 + j) * SG + c] = g;
            ua0 = ua1; ua1 = ua2; va0 = va1; va1 = va2;
            ub0 = ub1; ub1 = ub2; vb0 = vb1; vb1 = vb2;
        }
    }
    // tails: rows {0,1,66,67} x cols 0..67 (272) + rows 2..65 x cols 64..67 (256)
    #pragma unroll
    for (int p = 0; p < 3; p++) {
        int idx = tid + 256 * p;
        int r, c;
        if (idx < 272)      { int rr = idx / 68; c = idx % 68; r = (rr < 2) ? rr : 64 + rr; }
        else if (idx < 528) { int k = idx - 272; r = 2 + (k >> 2); c = 64 + (k & 3); }
        else break;
        float sx, sy;
        sobel_at(s_img, r, c, sx, sy);
        s_gm[r * SG + c] = sqrtf(sx * sx + sy * sy);
    }
    __syncthreads();

    // ---- P3: quant + NMS -> t codes; writes gx/gy/gm/orient planes (STG.64). ----
    // main: t rows 1..64, col pair c = 2tx+1 (t cols 1..64) == output pixels.
    {
        int r0 = 1 + 8 * ty, c = 2 * tx + 1;
        // gm window rows r..r+2, cols c..c+3
        const float* gp = s_gm + r0 * SG + c;
        float gA0 = gp[0], gA1 = gp[1], gA2 = gp[2], gA3 = gp[3];
        float gB0 = gp[SG], gB1 = gp[SG + 1], gB2 = gp[SG + 2], gB3 = gp[SG + 3];
        // img for sobel at gm-coords (r+1, c+1),(r+1, c+2): rows r+1..r+3, cols c+2..c+5
        const float* ip = s_img + (r0 + 1) * SI + (c + 2);
        float f0 = ip[0], f1 = ip[1], f2 = ip[2], f3 = ip[3];
        float ua0 = f2 - f0, va0 = 0.5f * (f0 + f2) + f1;
        float ub0 = f3 - f1, vb0 = 0.5f * (f1 + f3) + f2;
        f0 = ip[SI]; f1 = ip[SI + 1]; f2 = ip[SI + 2]; f3 = ip[SI + 3];
        float ua1 = f2 - f0, va1 = 0.5f * (f0 + f2) + f1;
        float ub1 = f3 - f1, vb1 = 0.5f * (f1 + f3) + f2;
        size_t obase = (size_t)b * CH + (size_t)(y0 + 8 * ty) * IW + (x0 + 2 * tx);
        #pragma unroll
        for (int j = 0; j < 8; j++) {
            int r = r0 + j;
            const float* gq = s_gm + (r + 2) * SG + c;
            float gC0 = gq[0], gC1 = gq[1], gC2 = gq[2], gC3 = gq[3];
            const float* rp = ip + (j + 2) * SI;
            f0 = rp[0]; f1 = rp[1]; f2 = rp[2]; f3 = rp[3];
            float ua2 = f2 - f0, va2 = 0.5f * (f0 + f2) + f1;
            float ub2 = f3 - f1, vb2 = 0.5f * (f1 + f3) + f2;
            float sxa = (0.5f * (ua0 + ua2) + ua1) * INV3;
            float sya = (va2 - va0) * INV3;
            float sxb = (0.5f * (ub0 + ub2) + ub1) * INV3;
            float syb = (vb2 - vb0) * INV3;
            int qa = quant_q(sxa, sya);
            int qb = quant_q(sxb, syb);
            int ca = nms_code(qa & 3, gB1, gA0, gA1, gA2, gB0, gB2, gC0, gC1, gC2);
            int cb = nms_code(qb & 3, gB2, gA1, gA2, gA3, gB1, gB3, gC1, gC2, gC3);
            s_t[r * ST + c]     = (unsigned char)ca;
            s_t[r * ST + c + 1] = (unsigned char)cb;
            float qva = (float)qa * 45.0f;
            if (sxa == 0.0f && sya == 0.0f) qva = __int_as_float(0x7fc00000);
            float qvb = (float)qb * 45.0f;
            if (sxb == 0.0f && syb == 0.0f) qvb = __int_as_float(0x7fc00000);
            size_t o = obase + (size_t)j * IW;
            __stcs((float2*)(o_gx + o), make_float2(sxa, sxb));
            __stcs((float2*)(o_gy + o), make_float2(sya, syb));
            __stcs((float2*)(o_gm + o), make_float2(gB1, gB2));
            __stcs((float2*)(o_or + o), make_float2(qva, qvb));
            gA0 = gB0; gA1 = gB1; gA2 = gB2; gA3 = gB3;
            gB0 = gC0; gB1 = gC1; gB2 = gC2; gB3 = gC3;
            ua0 = ua1; ua1 = ua2; va0 = va1; va1 = va2;
            ub0 = ub1; ub1 = ub2; vb0 = vb1; vb1 = vb2;
        }
    }
    // halo t: rows {0,65} x cols 0..65 (132) + cols {0,65} x rows 1..64 (128)
    #pragma unroll
    for (int p = 0; p < 2; p++) {
        int idx = tid + 256 * p;
        int r, c;
        if (idx < 132)      { int rr = idx / 66; c = idx % 66; r = rr ? 65 : 0; }
        else if (idx < 260) { int k = idx - 132; r = 1 + (k >> 1); c = (k & 1) ? 65 : 0; }
        else break;
        float sx, sy;
        sobel_at(s_img, r + 1, c + 1, sx, sy);
        const float* gp = s_gm + r * SG + c;
        int k2 = quant_q(sx, sy) & 3;
        int code = nms_code(k2, gp[SG + 1], gp[0], gp[1], gp[2], gp[SG], gp[SG + 2],
                            gp[2 * SG], gp[2 * SG + 1], gp[2 * SG + 2]);
        s_t[r * ST + c] = (unsigned char)code;
    }
    __syncthreads();

    // ---- P4: thin-edges (integer hysteresis). rows 8ty..8ty+7, col pair 2tx ----
    {
        int r0 = 8 * ty;
        const unsigned char* tp = s_t + r0 * ST + 2 * tx;   // bytes 2tx..2tx+3
        uchar2 p01 = *(const uchar2*)tp;
        uchar2 p23 = *(const uchar2*)(tp + 2);
        int sa0 = p01.x + p01.y + p23.x, sb0 = p01.y + p23.x + p23.y;
        p01 = *(const uchar2*)(tp + ST);
        p23 = *(const uchar2*)(tp + ST + 2);
        int sa1 = p01.x + p01.y + p23.x, sb1 = p01.y + p23.x + p23.y;
        int tca = p01.y, tcb = p23.x;
        size_t obase = (size_t)b * CH + (size_t)(y0 + r0) * IW + (x0 + 2 * tx);
        #pragma unroll
        for (int j = 0; j < 8; j++) {
            p01 = *(const uchar2*)(tp + (j + 2) * ST);
            p23 = *(const uchar2*)(tp + (j + 2) * ST + 2);
            int sa2 = p01.x + p01.y + p23.x, sb2 = p01.y + p23.x + p23.y;
            int Sa = sa0 + sa1 + sa2, Sb = sb0 + sb1 + sb2;
            float tea = (tca == 2 || (tca == 1 && Sa >= 2)) ? 1.0f : 0.0f;
            float teb = (tcb == 2 || (tcb == 1 && Sb >= 2)) ? 1.0f : 0.0f;
            __stcs((float2*)(o_te + obase + (size_t)j * IW), make_float2(tea, teb));
            sa0 = sa1; sa1 = sa2; sb0 = sb1; sb1 = sb2;
            tca = p01.y; tcb = p23.x;
        }
    }
}

// ======================= edge (scalar) =======================
__device__ __forceinline__ void body_edge(
    const float* __restrict__ imgb, float* __restrict__ out,
    int b, int x0, int y0, int tid,
    float* __restrict__ s_img, float* __restrict__ s_gm, unsigned char* __restrict__ s_t)
{
    const size_t plane = (size_t)NB * CH;
    float* o_gx = out;
    float* o_gy = out + plane;
    float* o_gm = out + 2 * plane;
    float* o_or = out + 3 * plane;
    float* o_te = out + 4 * plane;

    // P1: 70x72 with zero padding
    #pragma unroll
    for (int p = 0; p < 20; p++) {
        int idx = tid + 256 * p;
        if (idx < 5040) {
            int r = idx / 72, c = idx % 72;
            int gy = y0 - 3 + r, gx = x0 - 4 + c;
            float v = 0.0f;
            if ((unsigned)gy < IH && (unsigned)gx < IW) {
                const float* q = imgb + (size_t)gy * IW + gx;
                v = q[0] + q[CH] + q[2 * CH];
            }
            s_img[r * SI + c] = v;
        }
    }
    __syncthreads();

    // P2: gm 68x68, zero outside image
    #pragma unroll
    for (int p = 0; p < 19; p++) {
        int idx = tid + 256 * p;
        if (idx < 4624) {
            int r = idx / 68, c = idx % 68;
            float sx, sy;
            sobel_at(s_img, r, c, sx, sy);
            float gm = sqrtf(sx * sx + sy * sy);
            int gy = y0 - 2 + r, gx = x0 - 2 + c;
            if (!((unsigned)gy < IH && (unsigned)gx < IW)) gm = 0.f;
            s_gm[r * SG + c] = gm;
        }
    }
    __syncthreads();

    // P3: t codes 66x66 (zero outside image) + output planes for t rows/cols 1..64
    #pragma unroll
    for (int p = 0; p < 18; p++) {
        int idx = tid + 256 * p;
        if (idx < 4356) {
            int r = idx / 66, c = idx % 66;
            float sx, sy;
            sobel_at(s_img, r + 1, c + 1, sx, sy);
            const float* gp = s_gm + r * SG + c;
            float gmc = gp[SG + 1];
            int q = quant_q(sx, sy);
            int code = nms_code(q & 3, gmc, gp[0], gp[1], gp[2], gp[SG], gp[SG + 2],
                                gp[2 * SG], gp[2 * SG + 1], gp[2 * SG + 2]);
            int gy = y0 - 1 + r, gx = x0 - 1 + c;
            bool in_img = ((unsigned)gy < IH && (unsigned)gx < IW);
            if (!in_img) code = 0;
            s_t[r * ST + c] = (unsigned char)code;
            if (r >= 1 && r <= 64 && c >= 1 && c <= 64) {  // output pixel (in-image)
                float qv = (float)q * 45.0f;
                if (sx == 0.0f && sy == 0.0f) qv = __int_as_float(0x7fc00000);
                size_t o = (size_t)b * CH + (size_t)gy * IW + gx;
                __stcs(o_gx + o, sx);
                __stcs(o_gy + o, sy);
                __stcs(o_gm + o, gmc);
                __stcs(o_or + o, qv);
            }
        }
    }
    __syncthreads();

    // P4: thin-edges 64x64 (integer hysteresis)
    #pragma unroll
    for (int p = 0; p < 16; p++) {
        int idx = tid + 256 * p;
        int iy = idx >> 6, ix = idx & 63;
        const unsigned char* tp = s_t + iy * ST + ix;
        int S = tp[0] + tp[1] + tp[2]
              + tp[ST] + tp[ST + 1] + tp[ST + 2]
              + tp[2 * ST] + tp[2 * ST + 1] + tp[2 * ST + 2];
        int tc = tp[ST + 1];
        float te = (tc == 2 || (tc == 1 && S >= 2)) ? 1.0f : 0.0f;
        __stcs(o_te + (size_t)b * CH + (size_t)(y0 + iy) * IW + (x0 + ix), te);
    }
}

__global__ __launch_bounds__(256)
void canny_fused_kernel(const float* __restrict__ img, float* __restrict__ out)
{
    __shared__ float s_img[70 * SI];                 // 20160 B
    __shared__ float s_gm [68 * SG + 8];             // 19616 B
    __shared__ unsigned char s_t[66 * ST + 8];       //  4760 B

    const int b  = blockIdx.z;
    const int x0 = blockIdx.x * TS;
    const int y0 = blockIdx.y * TS;
    const int tx = threadIdx.x;
    const int ty = threadIdx.y;
    const int tid = ty * 32 + tx;

    const float* imgb = img + (size_t)b * 3 * CH;

    const bool edge = (x0 == 0) || (y0 == 0) || (x0 + TS == IW) || (y0 + TS == IH);
    if (edge)
        body_edge(imgb, out, b, x0, y0, tid, s_img, s_gm, s_t);
    else
        body_int(imgb, out, b, x0, y0, tx, ty, tid, s_img, s_gm, s_t);
}

extern "C" void kernel_launch(void* const* d_in, const int* in_sizes, int n_in,
                              void* d_out, int out_size)
{
    const float* img = (const float*)d_in[0];
    float* out = (float*)d_out;
    dim3 block(32, 8, 1);
    dim3 grid(IW / TS, IH / TS, NB);
    canny_fused_kernel<<<grid, block>>>(img, out);
}

// round 11
// speedup vs baseline: 1.2509x; 1.2509x over previous
#include <cuda_runtime.h>
#include <cuda_bf16.h>
#include <math.h>

#define IH 1024
#define IW 1024
#define NB 8
#define TW 32
#define TH 64
#define SIW 40   // s_img row stride; col c <-> gx = x0-4+c, row r <-> gy = y0-3+r
#define SW  36   // s_gm / s_t row stride

// tan((2k+1)*pi/16)
#define T0 0.1989123673796580f
#define T1 0.6681786379192989f
#define T2 1.4966057626654890f
#define T3 5.0273394921258481f
#define INV3 0.3333333333333333f

__device__ __forceinline__ int quant_q(float sx, float sy) {
    float ax = fabsf(sx), ay = fabsf(sy);
    int mm = (int)(ay > T0 * ax) + (int)(ay > T1 * ax)
           + (int)(ay > T2 * ax) + (int)(ay > T3 * ax);
    int neg = (__float_as_int(sx) ^ __float_as_int(sy)) < 0;
    return neg ? 4 - mm : 4 + mm;
}

// sobel at gm-coord (R,C): taps s_img rows R..R+2, cols C+1..C+3 (canonical u/v form)
__device__ __forceinline__ void sobel_at(const float* __restrict__ s_img, int R, int C,
                                         float& sx, float& sy) {
    const float* ip = s_img + R * SIW + (C + 1);
    float a0 = ip[0],       a1 = ip[1],           a2 = ip[2];
    float b0 = ip[SIW],                           b2 = ip[SIW + 2];
    float c0 = ip[2 * SIW], c1 = ip[2 * SIW + 1], c2 = ip[2 * SIW + 2];
    float u0 = a2 - a0, v0 = 0.5f * (a0 + a2) + a1;
    float u1 = b2 - b0;
    float u2 = c2 - c0, v2 = 0.5f * (c0 + c2) + c1;
    sx = (0.5f * (u0 + u2) + u1) * INV3;
    sy = (v2 - v0) * INV3;
}

// thin-edge code {0,1,2}; t = code * 0.5 exactly
__device__ __forceinline__ int nms_code(int k, float gmc,
                                        float g00, float g01, float g02,
                                        float g10,            float g12,
                                        float g20, float g21, float g22) {
    float mx0 = fmaxf(g10, g12);   // k=0: (0,±1)
    float mx1 = fmaxf(g02, g20);   // k=1: (-1,1)/(1,-1)
    float mx2 = fmaxf(g01, g21);   // k=2: (±1,0)
    float mx3 = fmaxf(g00, g22);   // k=3: (-1,-1)/(1,1)
    float mxa = (k & 1) ? mx1 : mx0;
    float mxb = (k & 1) ? mx3 : mx2;
    float mx  = (k & 2) ? mxb : mxa;
    float thin = (gmc > mx) ? gmc : 0.0f;
    return (int)(thin > 0.5f) + (int)(thin > 1.0f);
}

template<bool EDGE>
__device__ __forceinline__ void body(
    const float* __restrict__ imgb, float* __restrict__ out,
    int b, int x0, int y0, int tx, int ty, int tid,
    float* __restrict__ s_img, float* __restrict__ s_gm,
    unsigned char* __restrict__ s_t)
{
    // ---- P1: channel-summed image, rows 0..69 (gy=y0-3+r) x cols 0..39 (gx=x0-4+c)
    if (!EDGE) {
        const float4* base = (const float4*)(imgb + (size_t)(y0 - 3) * IW + (x0 - 4));
        const int CH4 = IH * IW / 4;
        #pragma unroll
        for (int p = 0; p < 3; p++) {
            int idx = tid + 256 * p;
            if (idx < 700) {
                int r = idx / 10, c4 = idx % 10;
                const float4* ptr = base + r * (IW / 4) + c4;
                float4 v0 = ptr[0], v1 = ptr[CH4], v2 = ptr[2 * CH4];
                float4 s;
                s.x = v0.x + v1.x + v2.x; s.y = v0.y + v1.y + v2.y;
                s.z = v0.z + v1.z + v2.z; s.w = v0.w + v1.w + v2.w;
                *(float4*)&s_img[r * SIW + c4 * 4] = s;
            }
        }
    } else {
        #pragma unroll
        for (int p = 0; p < 11; p++) {
            int idx = tid + 256 * p;
            if (idx < 2800) {
                int r = idx / 40, c = idx % 40;
                int gy = y0 - 3 + r, gx = x0 - 4 + c;
                float v = 0.0f;
                if ((unsigned)gy < IH && (unsigned)gx < IW) {
                    size_t o = (size_t)gy * IW + gx;
                    v = imgb[o] + imgb[o + IH * IW] + imgb[o + 2 * IH * IW];
                }
                s_img[r * SIW + c] = v;
            }
        }
    }
    __syncthreads();

    // ---- P2: gm only. row r <-> gy=y0-2+r (0..67), col c <-> gx=x0-2+c (0..35)
    auto p2_at = [&](int r, int c) {
        float sx, sy;
        sobel_at(s_img, r, c, sx, sy);
        float gm = sqrtf(sx * sx + sy * sy);
        if (EDGE) {
            int gy = y0 - 2 + r, gx = x0 - 2 + c;
            if (!((unsigned)gy < IH && (unsigned)gx < IW)) gm = 0.f;
        }
        s_gm[r * SW + c] = gm;
    };
    {   // main rolling: rows 2..65, col tx
        int r0 = 2 + 8 * ty, c = tx;
        const float* ip = s_img + r0 * SIW + (c + 1);
        float a0 = ip[0], a1 = ip[1], a2 = ip[2];
        float u0 = a2 - a0, v0 = 0.5f * (a0 + a2) + a1;
        float b0 = ip[SIW], b1 = ip[SIW + 1], b2 = ip[SIW + 2];
        float u1 = b2 - b0, v1 = 0.5f * (b0 + b2) + b1;
        #pragma unroll
        for (int j = 0; j < 8; j++) {
            const float* rp = ip + (j + 2) * SIW;
            float c0 = rp[0], c1 = rp[1], c2 = rp[2];
            float u2 = c2 - c0, v2 = 0.5f * (c0 + c2) + c1;
            float sx = (0.5f * (u0 + u2) + u1) * INV3;
            float sy = (v2 - v0) * INV3;
            float gm = sqrtf(sx * sx + sy * sy);
            int r = r0 + j;
            if (EDGE) {
                int gy = y0 - 2 + r, gx = x0 - 2 + c;
                if (!((unsigned)gy < IH && (unsigned)gx < IW)) gm = 0.f;
            }
            s_gm[r * SW + c] = gm;
            u0 = u1; u1 = u2; v0 = v1; v1 = v2;
        }
    }
    if (tid < 144) {            // tail A: rows {0,1,66,67} x cols 0..35
        int rr = tid / 36, c = tid % 36;
        p2_at((rr < 2) ? rr : 64 + rr, c);
    }
    {                           // tail B: rows 2..65 x cols 32..35 (exactly 256)
        p2_at(2 + (tid >> 2), 32 + (tid & 3));
    }
    __syncthreads();

    // ---- P3: quant + NMS -> t codes; ALSO writes gx/gy/gm/orient planes.
    // t row r <-> gy=y0-1+r (0..65), col c <-> gx=x0-1+c (0..33).
    const size_t plane = (size_t)NB * IH * IW;
    float* o_gx = out;
    float* o_gy = out + plane;
    float* o_gm = out + 2 * plane;
    float* o_or = out + 3 * plane;
    float* o_te = out + 4 * plane;

    auto p3_halo = [&](int r, int c) {   // halo t only, no gmem write
        float sx, sy;
        sobel_at(s_img, r + 1, c + 1, sx, sy);
        const float* gp = s_gm + r * SW + c;
        int k = quant_q(sx, sy) & 3;
        int code = nms_code(k, gp[SW + 1], gp[0], gp[1], gp[2], gp[SW], gp[SW + 2],
                            gp[2 * SW], gp[2 * SW + 1], gp[2 * SW + 2]);
        if (EDGE) {
            int gy = y0 - 1 + r, gx = x0 - 1 + c;
            if (!((unsigned)gy < IH && (unsigned)gx < IW)) code = 0;
        }
        s_t[r * SW + c] = (unsigned char)code;
    };
    {   // main rolling: rows 1..64, col c = tx+1 (pixel == output pixel, in-image)
        int r0 = 1 + 8 * ty, c = tx + 1;
        const float* gp = s_gm + r0 * SW + c;
        float gA0 = gp[0],  gA1 = gp[1],      gA2 = gp[2];
        float gB0 = gp[SW], gB1 = gp[SW + 1], gB2 = gp[SW + 2];
        const float* ip = s_img + (r0 + 1) * SIW + (c + 2);
        float a0 = ip[0], a1 = ip[1], a2 = ip[2];
        float u0 = a2 - a0, v0 = 0.5f * (a0 + a2) + a1;
        float b0 = ip[SIW], b1 = ip[SIW + 1], b2 = ip[SIW + 2];
        float u1 = b2 - b0, v1 = 0.5f * (b0 + b2) + b1;
        size_t obase = (size_t)b * IH * IW + (size_t)(y0 + 8 * ty) * IW + (x0 + tx);
        #pragma unroll
        for (int j = 0; j < 8; j++) {
            int r = r0 + j;
            const float* gq = s_gm + (r + 2) * SW + c;
            float gC0 = gq[0], gC1 = gq[1], gC2 = gq[2];
            const float* rp = ip + (j + 2) * SIW;
            float c0 = rp[0], c1 = rp[1], c2 = rp[2];
            float u2 = c2 - c0, v2 = 0.5f * (c0 + c2) + c1;
            float sx = (0.5f * (u0 + u2) + u1) * INV3;
            float sy = (v2 - v0) * INV3;
            int q = quant_q(sx, sy);
            int code = nms_code(q & 3, gB1, gA0, gA1, gA2, gB0, gB2, gC0, gC1, gC2);
            s_t[r * SW + c] = (unsigned char)code;
            float qv = (float)q * 45.0f;
            if (sx == 0.0f && sy == 0.0f) qv = __int_as_float(0x7fc00000);
            size_t o = obase + (size_t)j * IW;
            __stcs(o_gx + o, sx);
            __stcs(o_gy + o, sy);
            __stcs(o_gm + o, gB1);
            __stcs(o_or + o, qv);
            gA0 = gB0; gA1 = gB1; gA2 = gB2;
            gB0 = gC0; gB1 = gC1; gB2 = gC2;
            u0 = u1; u1 = u2; v0 = v1; v1 = v2;
        }
    }
    if (tid < 68) {             // tail A: rows {0,65} x cols 0..33
        int rr = tid / 34, c = tid % 34;
        p3_halo(rr ? 65 : 0, c);
    } else if (tid < 196) {     // tail B: rows 1..64 x cols {0,33}
        int k2 = tid - 68;
        p3_halo(1 + (k2 >> 1), (k2 & 1) ? 33 : 0);
    }
    __syncthreads();

    // ---- P4: thin-edges plane (integer hysteresis). rows 8ty..8ty+7, col tx.
    {
        int r0 = 8 * ty, ix = tx;
        const unsigned char* tp = s_t + r0 * SW + ix;
        int rs0 = tp[0]  + tp[1]      + tp[2];
        int rs1 = tp[SW] + tp[SW + 1] + tp[SW + 2];
        size_t obase = (size_t)b * IH * IW + (size_t)(y0 + r0) * IW + (x0 + ix);
        #pragma unroll
        for (int j = 0; j < 8; j++) {
            const unsigned char* rp = tp + (j + 2) * SW;
            int rs2 = rp[0] + rp[1] + rp[2];
            int S = rs0 + rs1 + rs2;
            int tc = tp[(j + 1) * SW + 1];
            // sum*1.25 > 1  <=>  S >= 2 (S = 2*sum, integer); high <=> tc==2
            float te = (tc == 2 || (tc == 1 && S >= 2)) ? 1.0f : 0.0f;
            __stcs(o_te + obase + (size_t)j * IW, te);
            rs0 = rs1; rs1 = rs2;
        }
    }
}

__global__ __launch_bounds__(256, 6)
void canny_fused_kernel(const float* __restrict__ img, float* __restrict__ out)
{
    __shared__ float s_img[70 * SIW];            // 11200 B
    __shared__ float s_gm [68 * SW + 8];         //  9856 B
    __shared__ unsigned char s_t[66 * SW + 8];   //  2384 B  (total ~23.4 KB)

    const int b  = blockIdx.z;
    const int x0 = blockIdx.x * TW;
    const int y0 = blockIdx.y * TH;
    const int tx = threadIdx.x;
    const int ty = threadIdx.y;
    const int tid = ty * 32 + tx;

    const float* imgb = img + (size_t)b * 3 * IH * IW;

    const bool edge = (x0 == 0) || (y0 == 0) || (x0 + TW == IW) || (y0 + TH == IH);
    if (edge)
        body<true >(imgb, out, b, x0, y0, tx, ty, tid, s_img, s_gm, s_t);
    else
        body<false>(imgb, out, b, x0, y0, tx, ty, tid, s_img, s_gm, s_t);
}

extern "C" void kernel_launch(void* const* d_in, const int* in_sizes, int n_in,
                              void* d_out, int out_size)
{
    const float* img = (const float*)d_in[0];
    float* out = (float*)d_out;
    dim3 block(32, 8, 1);
    dim3 grid(IW / TW, IH / TH, NB);
    canny_fused_kernel<<<grid, block>>>(img, out);
}

// round 12
// speedup vs baseline: 1.2853x; 1.0275x over previous
#include <cuda_runtime.h>
#include <cuda_bf16.h>
#include <math.h>

#define IH 1024
#define IW 1024
#define NB 8
#define CH (IH * IW)
#define TW 32
#define TH 64
#define SIW 40   // s_img stride; col c <-> gx = x0-4+c, row r <-> gy = y0-3+r
#define SW  36   // s_gm / s_k / s_t stride
                 // s_gm/s_k: row r <-> gy = y0-2+r (0..67), col c <-> gx = x0-2+c (0..35)
                 // s_t:      row r <-> gy = y0-1+r (0..65), col c <-> gx = x0-1+c (0..33)

// tan((2k+1)*pi/16)
#define T0 0.1989123673796580f
#define T1 0.6681786379192989f
#define T2 1.4966057626654890f
#define T3 5.0273394921258481f
#define INV3 0.3333333333333333f

__device__ __forceinline__ int quant_q(float sx, float sy) {
    float ax = fabsf(sx), ay = fabsf(sy);
    int mm = (int)(ay > T0 * ax) + (int)(ay > T1 * ax)
           + (int)(ay > T2 * ax) + (int)(ay > T3 * ax);
    int neg = (__float_as_int(sx) ^ __float_as_int(sy)) < 0;
    return neg ? 4 - mm : 4 + mm;
}

// sobel at gm-coord (R,C): taps s_img rows R..R+2, cols C+1..C+3 (canonical u/v form)
__device__ __forceinline__ void sobel_at(const float* __restrict__ s_img, int R, int C,
                                         float& sx, float& sy) {
    const float* ip = s_img + R * SIW + (C + 1);
    float a0 = ip[0],       a1 = ip[1],           a2 = ip[2];
    float b0 = ip[SIW],                           b2 = ip[SIW + 2];
    float c0 = ip[2 * SIW], c1 = ip[2 * SIW + 1], c2 = ip[2 * SIW + 2];
    float u0 = a2 - a0, v0 = 0.5f * (a0 + a2) + a1;
    float u1 = b2 - b0;
    float u2 = c2 - c0, v2 = 0.5f * (c0 + c2) + c1;
    sx = (0.5f * (u0 + u2) + u1) * INV3;
    sy = (v2 - v0) * INV3;
}

// thin-edge code {0,1,2}; t = code * 0.5 exactly
__device__ __forceinline__ int nms_code(int k, float gmc,
                                        float g00, float g01, float g02,
                                        float g10,            float g12,
                                        float g20, float g21, float g22) {
    float mx0 = fmaxf(g10, g12);   // k=0: (0,±1)
    float mx1 = fmaxf(g02, g20);   // k=1: (-1,1)/(1,-1)
    float mx2 = fmaxf(g01, g21);   // k=2: (±1,0)
    float mx3 = fmaxf(g00, g22);   // k=3: (-1,-1)/(1,1)
    float mxa = (k & 1) ? mx1 : mx0;
    float mxb = (k & 1) ? mx3 : mx2;
    float mx  = (k & 2) ? mxb : mxa;
    float thin = (gmc > mx) ? gmc : 0.0f;
    return (int)(thin > 0.5f) + (int)(thin > 1.0f);
}

template<bool EDGE>
__device__ __forceinline__ void body(
    const float* __restrict__ imgb, float* __restrict__ out,
    int b, int x0, int y0, int tx, int ty, int tid,
    float* __restrict__ s_img, float* __restrict__ s_gm,
    unsigned char* __restrict__ s_k, unsigned char* __restrict__ s_t)
{
    const size_t plane = (size_t)NB * CH;
    float* o_gx = out;
    float* o_gy = out + plane;
    float* o_gm = out + 2 * plane;
    float* o_or = out + 3 * plane;
    float* o_te = out + 4 * plane;

    // ---- P1: channel-summed image, rows 0..69 x cols 0..39 ----
    if (!EDGE) {
        const float4* base = (const float4*)(imgb + (size_t)(y0 - 3) * IW + (x0 - 4));
        #pragma unroll
        for (int p = 0; p < 3; p++) {
            int idx = tid + 256 * p;
            if (idx < 700) {
                int r = idx / 10, c4 = idx % 10;
                const float4* ptr = base + r * (IW / 4) + c4;
                float4 v0 = ptr[0], v1 = ptr[CH / 4], v2 = ptr[2 * (CH / 4)];
                float4 s;
                s.x = v0.x + v1.x + v2.x; s.y = v0.y + v1.y + v2.y;
                s.z = v0.z + v1.z + v2.z; s.w = v0.w + v1.w + v2.w;
                *(float4*)&s_img[r * SIW + c4 * 4] = s;
            }
        }
    } else {
        #pragma unroll
        for (int p = 0; p < 11; p++) {
            int idx = tid + 256 * p;
            if (idx < 2800) {
                int r = idx / 40, c = idx % 40;
                int gy = y0 - 3 + r, gx = x0 - 4 + c;
                float v = 0.0f;
                if ((unsigned)gy < IH && (unsigned)gx < IW) {
                    size_t o = (size_t)gy * IW + gx;
                    v = imgb[o] + imgb[o + CH] + imgb[o + 2 * CH];
                }
                s_img[r * SIW + c] = v;
            }
        }
    }
    __syncthreads();

    // ---- P2: gm + k code; main pixels == output pixels -> write 4 planes ----
    auto p2_at = [&](int r, int c) {   // tails (may be out of image)
        float sx, sy;
        sobel_at(s_img, r, c, sx, sy);
        float gm = sqrtf(sx * sx + sy * sy);
        int q = quant_q(sx, sy);
        if (EDGE) {
            int gy = y0 - 2 + r, gx = x0 - 2 + c;
            if (!((unsigned)gy < IH && (unsigned)gx < IW)) gm = 0.f;
        }
        s_gm[r * SW + c] = gm;
        s_k[r * SW + c] = (unsigned char)(q & 3);
    };
    {   // main rolling: rows 2..65, col c = tx+2 (gx = x0+tx, always in-image)
        int r0 = 2 + 8 * ty, c = tx + 2;
        const float* ip = s_img + r0 * SIW + (c + 1);
        float a0 = ip[0], a1 = ip[1], a2 = ip[2];
        float u0 = a2 - a0, v0 = 0.5f * (a0 + a2) + a1;
        float b0 = ip[SIW], b1 = ip[SIW + 1], b2 = ip[SIW + 2];
        float u1 = b2 - b0, v1 = 0.5f * (b0 + b2) + b1;
        size_t obase = (size_t)b * CH + (size_t)(y0 + 8 * ty) * IW + (x0 + tx);
        #pragma unroll
        for (int j = 0; j < 8; j++) {
            const float* rp = ip + (j + 2) * SIW;
            float c0 = rp[0], c1 = rp[1], c2 = rp[2];
            float u2 = c2 - c0, v2 = 0.5f * (c0 + c2) + c1;
            float sx = (0.5f * (u0 + u2) + u1) * INV3;
            float sy = (v2 - v0) * INV3;
            float gm = sqrtf(sx * sx + sy * sy);
            int q = quant_q(sx, sy);
            int r = r0 + j;
            s_gm[r * SW + c] = gm;
            s_k[r * SW + c] = (unsigned char)(q & 3);
            float qv = (float)q * 45.0f;
            if (sx == 0.0f && sy == 0.0f) qv = __int_as_float(0x7fc00000);
            size_t o = obase + (size_t)j * IW;
            __stcs(o_gx + o, sx);
            __stcs(o_gy + o, sy);
            __stcs(o_gm + o, gm);
            __stcs(o_or + o, qv);
            u0 = u1; u1 = u2; v0 = v1; v1 = v2;
        }
    }
    // tails: rows {0,1,66,67} x cols 0..35 (144) + rows 2..65 x cols {0,1,34,35} (256)
    if (tid < 144) {
        int rr = tid / 36, c = tid % 36;
        p2_at((rr < 2) ? rr : 64 + rr, c);
    }
    {
        int r = 2 + (tid >> 2);
        int m = tid & 3;
        int c = (m < 2) ? m : 32 + m;   // 0,1,34,35
        p2_at(r, c);
    }
    __syncthreads();

    // ---- P3: pure NMS -> t codes. t(r,c): center gm/k at (r+1,c+1). ----
    auto p3_at = [&](int r, int c) {
        const float* gp = s_gm + r * SW + c;
        int k = s_k[(r + 1) * SW + (c + 1)];
        int code = nms_code(k, gp[SW + 1], gp[0], gp[1], gp[2], gp[SW], gp[SW + 2],
                            gp[2 * SW], gp[2 * SW + 1], gp[2 * SW + 2]);
        if (EDGE) {
            int gy = y0 - 1 + r, gx = x0 - 1 + c;
            if (!((unsigned)gy < IH && (unsigned)gx < IW)) code = 0;
        }
        s_t[r * SW + c] = (unsigned char)code;
    };
    {   // main rolling: rows 1..64, col c = tx+1 (always in-image, no guard)
        int r0 = 1 + 8 * ty, c = tx + 1;
        const float* gp = s_gm + r0 * SW + c;
        float gA0 = gp[0],  gA1 = gp[1],      gA2 = gp[2];
        float gB0 = gp[SW], gB1 = gp[SW + 1], gB2 = gp[SW + 2];
        const unsigned char* kp = s_k + (r0 + 1) * SW + (c + 1);
        #pragma unroll
        for (int j = 0; j < 8; j++) {
            int r = r0 + j;
            const float* gq = s_gm + (r + 2) * SW + c;
            float gC0 = gq[0], gC1 = gq[1], gC2 = gq[2];
            int k = kp[j * SW];
            int code = nms_code(k, gB1, gA0, gA1, gA2, gB0, gB2, gC0, gC1, gC2);
            s_t[r * SW + c] = (unsigned char)code;
            gA0 = gB0; gA1 = gB1; gA2 = gB2;
            gB0 = gC0; gB1 = gC1; gB2 = gC2;
        }
    }
    if (tid < 68) {             // tail A: rows {0,65} x cols 0..33
        int rr = tid / 34, c = tid % 34;
        p3_at(rr ? 65 : 0, c);
    } else if (tid < 196) {     // tail B: rows 1..64 x cols {0,33}
        int k2 = tid - 68;
        p3_at(1 + (k2 >> 1), (k2 & 1) ? 33 : 0);
    }
    __syncthreads();

    // ---- P4: thin-edges plane (integer hysteresis). rows 8ty..8ty+7, col tx ----
    {
        int r0 = 8 * ty, ix = tx;
        const unsigned char* tp = s_t + r0 * SW + ix;
        int rs0 = tp[0]  + tp[1]      + tp[2];
        int rs1 = tp[SW] + tp[SW + 1] + tp[SW + 2];
        size_t obase = (size_t)b * CH + (size_t)(y0 + r0) * IW + (x0 + ix);
        #pragma unroll
        for (int j = 0; j < 8; j++) {
            const unsigned char* rp = tp + (j + 2) * SW;
            int rs2 = rp[0] + rp[1] + rp[2];
            int S = rs0 + rs1 + rs2;
            int tc = tp[(j + 1) * SW + 1];
            // sum*1.25 > 1 <=> S >= 2 (S = 2*sum); high <=> tc==2
            float te = (tc == 2 || (tc == 1 && S >= 2)) ? 1.0f : 0.0f;
            __stcs(o_te + obase + (size_t)j * IW, te);
            rs0 = rs1; rs1 = rs2;
        }
    }
}

__global__ __launch_bounds__(256, 6)
void canny_fused_kernel(const float* __restrict__ img, float* __restrict__ out)
{
    __shared__ float s_img[70 * SIW];            // 11200 B
    __shared__ float s_gm [68 * SW + 8];         //  9856 B
    __shared__ unsigned char s_k[68 * SW + 8];   //  2456 B
    __shared__ unsigned char s_t[66 * SW + 8];   //  2384 B  (total ~25.9 KB)

    const int b  = blockIdx.z;
    const int x0 = blockIdx.x * TW;
    const int y0 = blockIdx.y * TH;
    const int tx = threadIdx.x;
    const int ty = threadIdx.y;
    const int tid = ty * 32 + tx;

    const float* imgb = img + (size_t)b * 3 * CH;

    const bool edge = (x0 == 0) || (y0 == 0) || (x0 + TW == IW) || (y0 + TH == IH);
    if (edge)
        body<true >(imgb, out, b, x0, y0, tx, ty, tid, s_img, s_gm, s_k, s_t);
    else
        body<false>(imgb, out, b, x0, y0, tx, ty, tid, s_img, s_gm, s_k, s_t);
}

extern "C" void kernel_launch(void* const* d_in, const int* in_sizes, int n_in,
                              void* d_out, int out_size)
{
    const float* img = (const float*)d_in[0];
    float* out = (float*)d_out;
    dim3 block(32, 8, 1);
    dim3 grid(IW / TW, IH / TH, NB);
    canny_fused_kernel<<<grid, block>>>(img, out);
}

// round 14
// speedup vs baseline: 1.2867x; 1.0010x over previous
#include <cuda_runtime.h>
#include <cuda_bf16.h>
#include <math.h>

#define IH 1024
#define IW 1024
#define NB 8
#define CH (IH * IW)
#define TW 32
#define TH 64
#define SIW 40   // s_img stride; col c <-> gx = x0-4+c, row r <-> gy = y0-3+r
#define SW  36   // s_gm / s_k / s_t stride
                 // s_gm/s_k: row r <-> gy = y0-2+r (0..67), col c <-> gx = x0-2+c (0..35)
                 // s_t:      row r <-> gy = y0-1+r (0..65), col c <-> gx = x0-1+c (0..33)

// tan((2k+1)*pi/16)
#define T0 0.1989123673796580f
#define T1 0.6681786379192989f
#define T2 1.4966057626654890f
#define T3 5.0273394921258481f
#define INV3 0.3333333333333333f

__device__ __forceinline__ int quant_q(float sx, float sy) {
    float ax = fabsf(sx), ay = fabsf(sy);
    int mm = (int)(ay > T0 * ax) + (int)(ay > T1 * ax)
           + (int)(ay > T2 * ax) + (int)(ay > T3 * ax);
    int neg = (__float_as_int(sx) ^ __float_as_int(sy)) < 0;
    return neg ? 4 - mm : 4 + mm;
}

// sobel at gm-coord (R,C): taps s_img rows R..R+2, cols C+1..C+3 (canonical u/v form)
__device__ __forceinline__ void sobel_at(const float* __restrict__ s_img, int R, int C,
                                         float& sx, float& sy) {
    const float* ip = s_img + R * SIW + (C + 1);
    float a0 = ip[0],       a1 = ip[1],           a2 = ip[2];
    float b0 = ip[SIW],                           b2 = ip[SIW + 2];
    float c0 = ip[2 * SIW], c1 = ip[2 * SIW + 1], c2 = ip[2 * SIW + 2];
    float u0 = a2 - a0, v0 = 0.5f * (a0 + a2) + a1;
    float u1 = b2 - b0;
    float u2 = c2 - c0, v2 = 0.5f * (c0 + c2) + c1;
    sx = (0.5f * (u0 + u2) + u1) * INV3;
    sy = (v2 - v0) * INV3;
}

// thin-edge code {0,1,2}; t = code * 0.5 exactly
__device__ __forceinline__ int nms_code(int k, float gmc,
                                        float g00, float g01, float g02,
                                        float g10,            float g12,
                                        float g20, float g21, float g22) {
    float mx0 = fmaxf(g10, g12);   // k=0: (0,±1)
    float mx1 = fmaxf(g02, g20);   // k=1: (-1,1)/(1,-1)
    float mx2 = fmaxf(g01, g21);   // k=2: (±1,0)
    float mx3 = fmaxf(g00, g22);   // k=3: (-1,-1)/(1,1)
    float mxa = (k & 1) ? mx1 : mx0;
    float mxb = (k & 1) ? mx3 : mx2;
    float mx  = (k & 2) ? mxb : mxa;
    float thin = (gmc > mx) ? gmc : 0.0f;
    return (int)(thin > 0.5f) + (int)(thin > 1.0f);
}

template<bool EDGE>
__device__ __forceinline__ void body(
    const float* __restrict__ imgb, float* __restrict__ out,
    int b, int x0, int y0, int tx, int ty, int tid,
    float* __restrict__ s_img, float* __restrict__ s_gm,
    unsigned char* __restrict__ s_k, unsigned char* __restrict__ s_t)
{
    const size_t plane = (size_t)NB * CH;
    float* o_gx = out;
    float* o_gy = out + plane;
    float* o_gm = out + 2 * plane;
    float* o_or = out + 3 * plane;
    float* o_te = out + 4 * plane;

    // ---- P1: channel-summed image, rows 0..69 x cols 0..39 ----
    if (!EDGE) {
        const float4* base = (const float4*)(imgb + (size_t)(y0 - 3) * IW + (x0 - 4));
        #pragma unroll
        for (int p = 0; p < 3; p++) {
            int idx = tid + 256 * p;
            if (idx < 700) {
                int r = idx / 10, c4 = idx % 10;
                const float4* ptr = base + r * (IW / 4) + c4;
                float4 v0 = ptr[0], v1 = ptr[CH / 4], v2 = ptr[2 * (CH / 4)];
                float4 s;
                s.x = v0.x + v1.x + v2.x; s.y = v0.y + v1.y + v2.y;
                s.z = v0.z + v1.z + v2.z; s.w = v0.w + v1.w + v2.w;
                *(float4*)&s_img[r * SIW + c4 * 4] = s;
            }
        }
    } else {
        #pragma unroll
        for (int p = 0; p < 11; p++) {
            int idx = tid + 256 * p;
            if (idx < 2800) {
                int r = idx / 40, c = idx % 40;
                int gy = y0 - 3 + r, gx = x0 - 4 + c;
                float v = 0.0f;
                if ((unsigned)gy < IH && (unsigned)gx < IW) {
                    size_t o = (size_t)gy * IW + gx;
                    v = imgb[o] + imgb[o + CH] + imgb[o + 2 * CH];
                }
                s_img[r * SIW + c] = v;
            }
        }
    }
    __syncthreads();

    // per-thread packed direction codes (P2 main rows) and t codes (P3 main rows)
    unsigned int kpack = 0;

    // ---- P2: gm (+k in register); main pixels == output pixels -> write 4 planes ----
    auto p2_at = [&](int r, int c) {   // tails (may be out of image); k to s_k
        float sx, sy;
        sobel_at(s_img, r, c, sx, sy);
        float gm = sqrtf(sx * sx + sy * sy);
        int q = quant_q(sx, sy);
        if (EDGE) {
            int gy = y0 - 2 + r, gx = x0 - 2 + c;
            if (!((unsigned)gy < IH && (unsigned)gx < IW)) gm = 0.f;
        }
        s_gm[r * SW + c] = gm;
        s_k[r * SW + c] = (unsigned char)(q & 3);
    };
    {   // main rolling: rows 2..65, col c = tx+2 (gx = x0+tx, always in-image)
        int r0 = 2 + 8 * ty, c = tx + 2;
        const float* ip = s_img + r0 * SIW + (c + 1);
        float a0 = ip[0], a1 = ip[1], a2 = ip[2];
        float u0 = a2 - a0, v0 = 0.5f * (a0 + a2) + a1;
        float b0 = ip[SIW], b1 = ip[SIW + 1], b2 = ip[SIW + 2];
        float u1 = b2 - b0, v1 = 0.5f * (b0 + b2) + b1;
        size_t obase = (size_t)b * CH + (size_t)(y0 + 8 * ty) * IW + (x0 + tx);
        #pragma unroll
        for (int j = 0; j < 8; j++) {
            const float* rp = ip + (j + 2) * SIW;
            float c0 = rp[0], c1 = rp[1], c2 = rp[2];
            float u2 = c2 - c0, v2 = 0.5f * (c0 + c2) + c1;
            float sx = (0.5f * (u0 + u2) + u1) * INV3;
            float sy = (v2 - v0) * INV3;
            float gm = sqrtf(sx * sx + sy * sy);
            int q = quant_q(sx, sy);
            s_gm[(r0 + j) * SW + c] = gm;
            kpack |= (unsigned int)(q & 3) << (2 * j);
            float qv = (float)q * 45.0f;
            if (sx == 0.0f && sy == 0.0f) qv = __int_as_float(0x7fc00000);
            size_t o = obase + (size_t)j * IW;
            __stcs(o_gx + o, sx);
            __stcs(o_gy + o, sy);
            __stcs(o_gm + o, gm);
            __stcs(o_or + o, qv);
            u0 = u1; u1 = u2; v0 = v1; v1 = v2;
        }
    }
    // tails: rows {0,1,66,67} x cols 0..35 (144) + rows 2..65 x cols {0,1,34,35} (256)
    if (tid < 144) {
        int rr = tid / 36, c = tid % 36;
        p2_at((rr < 2) ? rr : 64 + rr, c);
    }
    {
        int r = 2 + (tid >> 2);
        int m = tid & 3;
        int c = (m < 2) ? m : 32 + m;   // 0,1,34,35
        p2_at(r, c);
    }
    __syncthreads();

    // ---- P3: pure NMS -> t codes (center k from kpack; center t kept in tpack) ----
    unsigned int tpack = 0;
    auto p3_at = [&](int r, int c) {    // tails: k from s_k (written by P2 tails)
        const float* gp = s_gm + r * SW + c;
        int k = s_k[(r + 1) * SW + (c + 1)];
        int code = nms_code(k, gp[SW + 1], gp[0], gp[1], gp[2], gp[SW], gp[SW + 2],
                            gp[2 * SW], gp[2 * SW + 1], gp[2 * SW + 2]);
        if (EDGE) {
            int gy = y0 - 1 + r, gx = x0 - 1 + c;
            if (!((unsigned)gy < IH && (unsigned)gx < IW)) code = 0;
        }
        s_t[r * SW + c] = (unsigned char)code;
    };
    {   // main rolling: rows 1..64, col c = tx+1 (always in-image)
        int r0 = 1 + 8 * ty, c = tx + 1;
        const float* gp = s_gm + r0 * SW + c;
        float gA0 = gp[0],  gA1 = gp[1],      gA2 = gp[2];
        float gB0 = gp[SW], gB1 = gp[SW + 1], gB2 = gp[SW + 2];
        #pragma unroll
        for (int j = 0; j < 8; j++) {
            int r = r0 + j;
            const float* gq = s_gm + (r + 2) * SW + c;
            float gC0 = gq[0], gC1 = gq[1], gC2 = gq[2];
            int k = (kpack >> (2 * j)) & 3;     // k at (r+1, c+1) == own P2 row j
            int code = nms_code(k, gB1, gA0, gA1, gA2, gB0, gB2, gC0, gC1, gC2);
            s_t[r * SW + c] = (unsigned char)code;
            tpack |= (unsigned int)code << (2 * j);
            gA0 = gB0; gA1 = gB1; gA2 = gB2;
            gB0 = gC0; gB1 = gC1; gB2 = gC2;
        }
    }
    if (tid < 68) {             // tail A: rows {0,65} x cols 0..33
        int rr = tid / 34, c = tid % 34;
        p3_at(rr ? 65 : 0, c);
    } else if (tid < 196) {     // tail B: rows 1..64 x cols {0,33}
        int k2 = tid - 68;
        p3_at(1 + (k2 >> 1), (k2 & 1) ? 33 : 0);
    }
    __syncthreads();

    // ---- P4: thin-edges (integer hysteresis); center tc from tpack ----
    {
        int r0 = 8 * ty, ix = tx;
        const unsigned char* tp = s_t + r0 * SW + ix;
        int rs0 = tp[0]  + tp[1]      + tp[2];
        int rs1 = tp[SW] + tp[SW + 1] + tp[SW + 2];
        size_t obase = (size_t)b * CH + (size_t)(y0 + r0) * IW + (x0 + ix);
        #pragma unroll
        for (int j = 0; j < 8; j++) {
            const unsigned char* rp = tp + (j + 2) * SW;
            int rs2 = rp[0] + rp[1] + rp[2];
            int S = rs0 + rs1 + rs2;
            int tc = (tpack >> (2 * j)) & 3;    // t at (8ty+j+1, tx+1) == own P3 row j
            // sum*1.25 > 1 <=> S >= 2 (S = 2*sum); high <=> tc==2
            float te = (tc == 2 || (tc == 1 && S >= 2)) ? 1.0f : 0.0f;
            __stcs(o_te + obase + (size_t)j * IW, te);
            rs0 = rs1; rs1 = rs2;
        }
    }
}

__global__ __launch_bounds__(256, 6)
void canny_fused_kernel(const float* __restrict__ img, float* __restrict__ out)
{
    __shared__ float s_img[70 * SIW];            // 11200 B
    __shared__ float s_gm [68 * SW + 8];         //  9856 B
    __shared__ unsigned char s_k[68 * SW + 8];   //  2456 B (tails only)
    __shared__ unsigned char s_t[66 * SW + 8];   //  2384 B

    const int b  = blockIdx.z;
    const int x0 = blockIdx.x * TW;
    const int y0 = blockIdx.y * TH;
    const int tx = threadIdx.x;
    const int ty = threadIdx.y;
    const int tid = ty * 32 + tx;

    const float* imgb = img + (size_t)b * 3 * CH;

    const bool edge = (x0 == 0) || (y0 == 0) || (x0 + TW == IW) || (y0 + TH == IH);
    if (edge)
        body<true >(imgb, out, b, x0, y0, tx, ty, tid, s_img, s_gm, s_k, s_t);
    else
        body<false>(imgb, out, b, x0, y0, tx, ty, tid, s_img, s_gm, s_k, s_t);
}

extern "C" void kernel_launch(void* const* d_in, const int* in_sizes, int n_in,
                              void* d_out, int out_size)
{
    const float* img = (const float*)d_in[0];
    float* out = (float*)d_out;
    dim3 block(32, 8, 1);
    dim3 grid(IW / TW, IH / TH, NB);
    canny_fused_kernel<<<grid, block>>>(img, out);
}